// round 1
// baseline (speedup 1.0000x reference)
#include <cuda_runtime.h>
#include <cstdint>

#define TB     512
#define VV     32000
#define NQ     (VV/4)
#define NROWS  4096
#define KSEL   100
#define CAP    2048
#define NB     2048
#define NEG_INF (-3.402823466e38f)

struct SmemLayout {
  unsigned tkeys[VV];        // teacher keys (order-preserving map of float)
  unsigned hist[NB];
  unsigned cand_key[CAP];
  unsigned cand_idx[CAP];
  unsigned sel_key[KSEL + 28];
  unsigned sel_idx[KSEL + 28];
  unsigned tie_idx[64];
  float    red[16];
  float    redb[16];
  unsigned find_b, find_kk, find_candn;
  unsigned cand_cnt, n_sel, n_tie, sel_n;
  int      label32, label_valid;
  float    lse_s;
};

__device__ float g_ce[NROWS];
__device__ float g_kl[NROWS];
__device__ int   g_valid[NROWS];

__device__ __forceinline__ unsigned f2k(float x){
  unsigned u = __float_as_uint(x);
  return (u & 0x80000000u) ? ~u : (u | 0x80000000u);
}
__device__ __forceinline__ float k2f(unsigned k){
  unsigned u = (k & 0x80000000u) ? (k & 0x7FFFFFFFu) : ~k;
  return __uint_as_float(u);
}

// Warp 0 only: find bin b (from top) s.t. count(bin > b) < kT <= count(bin >= b).
// Writes find_b, find_kk = kT - count(bin>b), find_candn = count(bin>=b).
__device__ __forceinline__ void warpFindBin(SmemLayout* sm, int nbins, unsigned kT){
  int lane  = threadIdx.x & 31;
  int chunk = nbins >> 5;
  int hiBin = nbins - 1 - chunk * lane;
  unsigned csum = 0;
  for (int j = 0; j < chunk; j++) csum += sm->hist[hiBin - j];
  unsigned inc = csum;
  #pragma unroll
  for (int o = 1; o < 32; o <<= 1){
    unsigned v = __shfl_up_sync(0xffffffffu, inc, o);
    if (lane >= o) inc += v;
  }
  unsigned bal = __ballot_sync(0xffffffffu, inc >= kT);
  int fl = bal ? (__ffs(bal) - 1) : 31;
  if (lane == fl){
    unsigned acc = inc - csum;
    int b = hiBin;
    unsigned h = 0;
    for (int j = 0; j < chunk; j++){
      h = sm->hist[b];
      acc += h;
      if (acc >= kT) break;
      b--;
    }
    sm->find_b     = (unsigned)b;
    sm->find_kk    = kT - (acc - h);
    sm->find_candn = acc;
  }
}

__device__ __forceinline__ float blkMax(SmemLayout* sm, float v){
  int lane = threadIdx.x & 31, w = threadIdx.x >> 5;
  #pragma unroll
  for (int o = 16; o; o >>= 1) v = fmaxf(v, __shfl_xor_sync(0xffffffffu, v, o));
  __syncthreads();
  if (lane == 0) sm->red[w] = v;
  __syncthreads();
  float r = sm->red[0];
  #pragma unroll
  for (int i = 1; i < TB/32; i++) r = fmaxf(r, sm->red[i]);
  return r;
}

__device__ __forceinline__ float blkSum(SmemLayout* sm, float v){
  int lane = threadIdx.x & 31, w = threadIdx.x >> 5;
  #pragma unroll
  for (int o = 16; o; o >>= 1) v += __shfl_xor_sync(0xffffffffu, v, o);
  __syncthreads();
  if (lane == 0) sm->red[w] = v;
  __syncthreads();
  float r = 0.f;
  #pragma unroll
  for (int i = 0; i < TB/32; i++) r += sm->red[i];
  return r;
}

__global__ void __launch_bounds__(TB, 1)
row_kernel(const float* __restrict__ student,
           const float* __restrict__ teacher,
           const int*   __restrict__ labels32){
  extern __shared__ char smraw[];
  SmemLayout* sm = reinterpret_cast<SmemLayout*>(smraw);
  const int tid = threadIdx.x;
  const int row = blockIdx.x;

  for (int i = tid; i < NB; i += TB) sm->hist[i] = 0;
  if (tid == 0){
    sm->cand_cnt = 0; sm->n_sel = 0; sm->n_tie = 0;
    // dtype sniff: int64 labels have zero (or -1) high words at odd int32 slots
    int w1 = labels32[1], w3 = labels32[3], w5 = labels32[5];
    bool is64 = (w1==0||w1==-1) && (w3==0||w3==-1) && (w5==0||w5==-1);
    long long lab;
    if (is64){
      unsigned lo = (unsigned)labels32[2*row];
      int      hi = labels32[2*row+1];
      lab = ((long long)hi << 32) | (long long)lo;
    } else {
      lab = (long long)labels32[row];
    }
    int valid = (lab != -100LL);
    sm->label32     = valid ? (int)lab : 0;
    sm->label_valid = valid;
  }
  __syncthreads();

  const float4* srow = reinterpret_cast<const float4*>(student + (size_t)row * VV);
  const float4* trow = reinterpret_cast<const float4*>(teacher + (size_t)row * VV);

  // ---- single fused streaming pass: student online LSE, teacher keys+hist ----
  float m = NEG_INF, ssum = 0.f;
  for (int i = tid; i < NQ; i += TB){
    float4 s = __ldg(srow + i);
    float4 t = __ldg(trow + i);
    #pragma unroll
    for (int q = 0; q < 4; q++){
      float x = (q==0) ? s.x : (q==1) ? s.y : (q==2) ? s.z : s.w;
      if (x > m){ ssum = ssum * __expf(m - x) + 1.f; m = x; }
      else      { ssum += __expf(x - m); }
    }
    unsigned k0=f2k(t.x), k1=f2k(t.y), k2=f2k(t.z), k3=f2k(t.w);
    reinterpret_cast<uint4*>(sm->tkeys)[i] = make_uint4(k0,k1,k2,k3);
    atomicAdd(&sm->hist[k0>>21], 1u);
    atomicAdd(&sm->hist[k1>>21], 1u);
    atomicAdd(&sm->hist[k2>>21], 1u);
    atomicAdd(&sm->hist[k3>>21], 1u);
  }

  // ---- block combine (m, ssum) ----
  {
    int lane = tid & 31, w = tid >> 5;
    #pragma unroll
    for (int o = 16; o; o >>= 1){
      float om = __shfl_xor_sync(0xffffffffu, m,    o);
      float os = __shfl_xor_sync(0xffffffffu, ssum, o);
      float nm = fmaxf(m, om);
      ssum = ssum * __expf(m - nm) + os * __expf(om - nm);
      m = nm;
    }
    if (lane == 0){ sm->red[w] = m; sm->redb[w] = ssum; }
  }
  __syncthreads();
  if (tid == 0){
    float mm = sm->red[0], ss = sm->redb[0];
    for (int i = 1; i < TB/32; i++){
      float om = sm->red[i], os = sm->redb[i];
      float nm = fmaxf(mm, om);
      ss = ss * __expf(mm - nm) + os * __expf(om - nm);
      mm = nm;
    }
    sm->lse_s = mm + __logf(ss);
  }
  if (tid < 32) warpFindBin(sm, NB, KSEL);
  __syncthreads();

  unsigned b0 = sm->find_b, kk0 = sm->find_kk, candn0 = sm->find_candn;
  bool two = (candn0 > CAP);
  unsigned b1 = 0;
  if (two){
    for (int i = tid; i < NB; i += TB) sm->hist[i] = 0;
    __syncthreads();
    for (int i = tid; i < VV; i += TB){
      unsigned k = sm->tkeys[i];
      if ((k >> 21) == b0) atomicAdd(&sm->hist[(k >> 10) & 0x7FFu], 1u);
    }
    __syncthreads();
    if (tid < 32) warpFindBin(sm, NB, kk0);
    __syncthreads();
    b1 = sm->find_b;
  }

  // ---- collect candidates (all elements >= coarse threshold) ----
  for (int i = tid; i < VV; i += TB){
    unsigned k = sm->tkeys[i];
    unsigned top = k >> 21;
    bool take = two ? (top > b0 || (top == b0 && ((k >> 10) & 0x7FFu) >= b1))
                    : (top >= b0);
    if (take){
      unsigned p = atomicAdd(&sm->cand_cnt, 1u);
      if (p < CAP){ sm->cand_key[p] = k; sm->cand_idx[p] = (unsigned)i; }
    }
  }
  __syncthreads();
  unsigned candn = sm->cand_cnt; if (candn > CAP) candn = CAP;

  // ---- exact 100th-largest key among candidates: 3-level radix ----
  for (int i = tid; i < NB; i += TB) sm->hist[i] = 0;
  __syncthreads();
  for (unsigned c = tid; c < candn; c += TB)
    atomicAdd(&sm->hist[sm->cand_key[c] >> 21], 1u);
  __syncthreads();
  if (tid < 32) warpFindBin(sm, NB, KSEL);
  __syncthreads();
  unsigned bA = sm->find_b, kkA = sm->find_kk;

  for (int i = tid; i < NB; i += TB) sm->hist[i] = 0;
  __syncthreads();
  for (unsigned c = tid; c < candn; c += TB){
    unsigned k = sm->cand_key[c];
    if ((k >> 21) == bA) atomicAdd(&sm->hist[(k >> 10) & 0x7FFu], 1u);
  }
  __syncthreads();
  if (tid < 32) warpFindBin(sm, NB, kkA);
  __syncthreads();
  unsigned bB = sm->find_b, kkB = sm->find_kk;

  for (int i = tid; i < NB; i += TB) sm->hist[i] = 0;
  __syncthreads();
  for (unsigned c = tid; c < candn; c += TB){
    unsigned k = sm->cand_key[c];
    if ((k >> 21) == bA && ((k >> 10) & 0x7FFu) == bB)
      atomicAdd(&sm->hist[k & 0x3FFu], 1u);
  }
  __syncthreads();
  if (tid < 32) warpFindBin(sm, 1024, kkB);
  __syncthreads();
  unsigned T = (bA << 21) | (bB << 10) | sm->find_b;

  // ---- select: strictly greater + smallest-index ties ----
  for (unsigned c = tid; c < candn; c += TB){
    unsigned k = sm->cand_key[c];
    if (k > T){
      unsigned p = atomicAdd(&sm->n_sel, 1u);
      if (p < KSEL + 28){ sm->sel_key[p] = k; sm->sel_idx[p] = sm->cand_idx[c]; }
    } else if (k == T){
      unsigned p = atomicAdd(&sm->n_tie, 1u);
      if (p < 64) sm->tie_idx[p] = sm->cand_idx[c];
    }
  }
  __syncthreads();
  if (tid == 0){
    unsigned ns = sm->n_sel; if (ns > KSEL) ns = KSEL;
    int need = KSEL - (int)ns;
    int nt = (int)sm->n_tie; if (nt > 64) nt = 64;
    if (need > nt) need = nt;
    for (int a = 0; a < need; a++){
      int best = a;
      for (int b2 = a + 1; b2 < nt; b2++)
        if (sm->tie_idx[b2] < sm->tie_idx[best]) best = b2;
      unsigned tv = sm->tie_idx[a]; sm->tie_idx[a] = sm->tie_idx[best]; sm->tie_idx[best] = tv;
      sm->sel_key[ns + a] = T; sm->sel_idx[ns + a] = sm->tie_idx[a];
    }
    sm->sel_n = ns + (unsigned)need;
  }
  __syncthreads();

  // ---- epilogue: KL over top-k at temperature 5 ----
  int nsel = (int)sm->sel_n;
  bool act = (tid < nsel);
  float aval = NEG_INF, bval = NEG_INF;
  if (act){
    aval = k2f(sm->sel_key[tid]) * 0.2f;
    float sv = __ldg(student + (size_t)row * VV + sm->sel_idx[tid]);
    bval = sv * 0.2f;
  }
  float maxA = blkMax(sm, aval);
  float maxB = blkMax(sm, bval);
  float eA = act ? __expf(aval - maxA) : 0.f;
  float eB = act ? __expf(bval - maxB) : 0.f;
  float sA = blkSum(sm, eA);
  float sB = blkSum(sm, eB);
  float lseA = maxA + __logf(sA);
  float lseB = maxB + __logf(sB);
  float term = act ? (__expf(aval - lseA) * ((aval - lseA) - (bval - lseB))) : 0.f;
  float kl = blkSum(sm, term);

  if (tid == 0){
    int valid = sm->label_valid;
    float ce = 0.f, klo = 0.f;
    if (valid){
      float slab = __ldg(student + (size_t)row * VV + sm->label32);
      ce  = sm->lse_s - slab;
      klo = kl;
    }
    g_ce[row] = ce; g_kl[row] = klo; g_valid[row] = valid;
  }
}

__global__ void finalize_kernel(float* __restrict__ out, int out_size){
  __shared__ float rc[16], rk[16];
  __shared__ int   rv[16];
  int tid = threadIdx.x;
  float ce = 0.f, kl = 0.f; int nv = 0;
  for (int i = tid; i < NROWS; i += 512){ ce += g_ce[i]; kl += g_kl[i]; nv += g_valid[i]; }
  int lane = tid & 31, w = tid >> 5;
  #pragma unroll
  for (int o = 16; o; o >>= 1){
    ce += __shfl_xor_sync(0xffffffffu, ce, o);
    kl += __shfl_xor_sync(0xffffffffu, kl, o);
    nv += __shfl_xor_sync(0xffffffffu, nv, o);
  }
  if (lane == 0){ rc[w] = ce; rk[w] = kl; rv[w] = nv; }
  __syncthreads();
  if (tid == 0){
    float tce = 0.f, tkl = 0.f; int tnv = 0;
    for (int i = 0; i < 16; i++){ tce += rc[i]; tkl += rk[i]; tnv += rv[i]; }
    float nvf = (float)(tnv > 0 ? tnv : 1);
    float cem = tce / nvf;
    float tcs = tkl / nvf * 25.f;               // * TEMPERATURE^2
    if (out_size > 0) out[0] = cem + 10.f * tcs; // + LAMBDA_TCS * tcs
    if (out_size > 1) out[1] = cem;
    if (out_size > 2) out[2] = tcs;
    if (out_size > 3) out[3] = 0.f;
  }
  for (int i = 4 + tid; i < out_size; i += 512) out[i] = 0.f;
}

extern "C" void kernel_launch(void* const* d_in, const int* in_sizes, int n_in,
                              void* d_out, int out_size){
  const float* student  = (const float*)d_in[0];
  const float* teacher  = (const float*)d_in[1];
  const int*   labels32 = (const int*)d_in[2];

  size_t smem = sizeof(SmemLayout);
  cudaFuncSetAttribute(row_kernel, cudaFuncAttributeMaxDynamicSharedMemorySize, (int)smem);

  row_kernel<<<NROWS, TB, smem>>>(student, teacher, labels32);
  finalize_kernel<<<1, 512>>>((float*)d_out, out_size);
}